// round 8
// baseline (speedup 1.0000x reference)
#include <cuda_runtime.h>
#include <cstddef>

#define TT 4096
#define KK 16
#define BB 32
#define LCH 16
#define NPOS (TT / LCH)            // 256 chunks per batch
#define NCHUNK (BB * NPOS)         // 8192 chunks
#define NPAIR (NCHUNK / 2)         // 4096 pairs (b, b+16)
#define RHO_C 0.001f
#define NEG_INF_C (-1000000.0f)
#define FLOORP 1e-10f

__device__ float g_S[NCHUNK * 256];   // per-chunk transfer matrix, [chunk][ROW][COL]
__device__ float g_v0[NCHUNK * 16];   // (rescaled) alpha entering each chunk

// ---------------------------------------------------------------------------
// Phase 1: transfer matrices + fused coalesced A writes.
// Block = 128 threads, handles chunk pair (bA, p) and (bA+16, p):
//   warps 0,1 : transfer matrix for chunk 0 / 1 (lanes 0-15 + mirror)
//   warps 2,3 : A-tensor writes for chunk 0 / 1 (whole-warp coalesced STG.128)
// ---------------------------------------------------------------------------
__global__ void __launch_bounds__(128) phase1_kernel(const float* __restrict__ em,
                                                     const float* __restrict__ bp,
                                                     float4* __restrict__ A4) {
    __shared__ float s_E[2][LCH * KK];
    __shared__ float s_cf[2][LCH * 8];
    const unsigned FULL = 0xffffffffu;
    int tid = threadIdx.x;
    int wid = tid >> 5, lane = tid & 31;
    int pk = blockIdx.x;
    int bA = pk >> 8;                 // 0..15
    int p  = pk & 255;

    // stage exp(emissions): 128 float4s, one per thread
    {
        int h = tid >> 6, idx = tid & 63;
        size_t bt = (size_t)(bA + h * 16) * TT + (size_t)p * LCH;
        float4 v = ((const float4*)(em + bt * KK))[idx];
        ((float4*)s_E[h])[idx] = make_float4(__expf(v.x), __expf(v.y), __expf(v.z), __expf(v.w));
    }
    // stage folded coefficients: 32 steps total, one per thread
    if (tid < 32) {
        int h = tid >> 4, i = tid & 15;
        size_t bt = (size_t)(bA + h * 16) * TT + (size_t)p * LCH;
        float bpt = bp[bt + i];
        float eta = fminf(fmaxf(0.02f + 0.33f * bpt, 0.001f), 0.95f);
        float stay = fmaxf((1.0f - eta) - RHO_C, 0.01f);
        float rm = (RHO_C + stay) + eta;
        float ir0 = 1.0f, irm = __fdividef(1.0f, rm), irl = 1.0f;   // r0 == rl == 1 exactly
        float4* cf = (float4*)&s_cf[h][i * 8];
        cf[0] = make_float4(eta * ir0 - FLOORP, eta * irm - FLOORP,
                            (1.0f - eta) * ir0 - FLOORP, stay * irm - FLOORP);
        cf[1] = make_float4((1.0f - RHO_C) * irl - FLOORP, RHO_C * irm - FLOORP,
                            RHO_C * irl - FLOORP, 0.0f);
    }
    __syncthreads();

    if (wid < 2) {
        // ---- transfer matrix for chunk `wid`: lane owns one column ----
        int hl = lane & 15;
        int b = bA + wid * 16;
        float w[16];
#pragma unroll
        for (int r = 0; r < 16; r++) w[r] = (r == hl) ? 1.0f : 0.0f;
        float csum = 1.0f;

        int t0 = (p == 0) ? 1 : 0;
        for (int tl = t0; tl < LCH; ++tl) {
            const float4* cf = (const float4*)&s_cf[wid][tl * 8];
            float4 ca = cf[0], cb = cf[1];
            const float* Et = &s_E[wid][tl * KK];
            float y[16];
#pragma unroll
            for (int r = 0; r < 16; r++) {
                float um1 = w[(r + 15) & 15];
                float up1 = w[(r + 1) & 15];
                float ec = (r == 0) ? 0.0f : (r == 1 ? ca.x : ca.y);
                float dc = (r == 0) ? ca.z : (r == 15 ? cb.x : ca.w);
                float rc = (r == 15) ? 0.0f : (r == 14 ? cb.z : cb.y);
                float q = fmaf(dc, w[r], fmaf(rc, up1, ec * um1));
                float P = fmaf(FLOORP, csum, q);
                y[r] = P * Et[r];
            }
            float a0 = (y[0] + y[4]) + (y[8] + y[12]);
            float a1 = (y[1] + y[5]) + (y[9] + y[13]);
            float a2 = (y[2] + y[6]) + (y[10] + y[14]);
            float a3 = (y[3] + y[7]) + (y[11] + y[15]);
            float cs2 = (a0 + a1) + (a2 + a3);
            float sc = __shfl_sync(FULL, cs2, 0, 16);
            float isc = __fdividef(1.0f, sc);
#pragma unroll
            for (int r = 0; r < 16; r++) w[r] = y[r] * isc;
            csum = cs2 * isc;
        }
        if (lane < 16) {      // store TRANSPOSED: [row][col] so phase2 reads rows
            float* out = g_S + (size_t)(b * NPOS + p) * 256 + hl;
#pragma unroll
            for (int r = 0; r < 16; r++) out[r * 16] = w[r];
        }
    } else {
        // ---- A writes for chunk h: whole warp per 1KB block, 2 STG.128/lane ----
        int h = wid - 2;
        size_t bt0 = (size_t)(bA + h * 16) * TT + (size_t)p * LCH;
        int f0 = lane, f1 = lane + 32;
        int r_0 = f0 >> 2, c0_0 = (f0 & 3) * 4;
        int r_1 = f1 >> 2, c0_1 = (f1 & 3) * 4;
        for (int i = 0; i < LCH; i++) {
            const float4* cf = (const float4*)&s_cf[h][i * 8];
            float4 ca = cf[0], cb = cf[1];
            float4* blk = A4 + (bt0 + i) * 64;
#pragma unroll
            for (int rep = 0; rep < 2; rep++) {
                int r  = rep ? r_1 : r_0;
                int c0 = rep ? c0_1 : c0_0;
                float dg = ((r == 0) ? ca.z : (r == 15) ? cb.x : ca.w) + FLOORP;
                float ev = ((r == 0) ? ca.x : ca.y) + FLOORP;          // A[r][r+1]
                float rv = ((r == 15) ? cb.z : cb.y) + FLOORP;         // A[r][r-1]
                float x[4];
#pragma unroll
                for (int q = 0; q < 4; q++) {
                    int j = c0 + q;
                    x[q] = (j == r) ? dg : (j == r + 1) ? ev : (j == r - 1) ? rv : 0.0f;
                }
                blk[rep ? f1 : f0] = make_float4(x[0], x[1], x[2], x[3]);
            }
        }
    }
}

// ---------------------------------------------------------------------------
// Phase 2: serial composition per batch (255 matvecs). Row-major S rows load
// as 4x LDG.128, double-buffered two ahead. Chain rescales every 2nd step;
// g_v0 stores are always rescaled (phase3 is scale-invariant anyway).
// ---------------------------------------------------------------------------
__device__ __forceinline__ float p2_matvec(const float4* s4, float x, unsigned FULL) {
    float y0 = 0.f, y1 = 0.f, y2 = 0.f, y3 = 0.f;
#pragma unroll
    for (int k = 0; k < 4; k++) {
        y0 = fmaf(s4[k].x, __shfl_sync(FULL, x, k * 4 + 0, 16), y0);
        y1 = fmaf(s4[k].y, __shfl_sync(FULL, x, k * 4 + 1, 16), y1);
        y2 = fmaf(s4[k].z, __shfl_sync(FULL, x, k * 4 + 2, 16), y2);
        y3 = fmaf(s4[k].w, __shfl_sync(FULL, x, k * 4 + 3, 16), y3);
    }
    return (y0 + y1) + (y2 + y3);
}

__global__ void __launch_bounds__(32) phase2_kernel(const float* __restrict__ em,
                                                    const float* __restrict__ mk) {
    int b = blockIdx.x;
    int lane = threadIdx.x;
    int j = lane & 15;
    const unsigned FULL = 0xffffffffu;

    float em0 = __ldg(em + (size_t)b * TT * KK);
    float emj = __ldg(em + (size_t)b * TT * KK + j);
    float m0 = __ldg(mk + (size_t)b * TT);
    float la0 = (j == 0) ? 0.0f : (NEG_INF_C + emj - em0);
    la0 = m0 * la0 + (1.0f - m0) * ((j == 0) ? 0.0f : NEG_INF_C);
    float u = expf(la0);
    if (lane < 16) g_v0[(size_t)(b * NPOS) * 16 + j] = u;

    const float* SbT = g_S + (size_t)b * NPOS * 256;
    float4 bufA[4], bufB[4];
#pragma unroll
    for (int k = 0; k < 4; k++) {
        bufA[k] = *(const float4*)(SbT + 0 * 256 + j * 16 + k * 4);
        bufB[k] = *(const float4*)(SbT + 1 * 256 + j * 16 + k * 4);
    }

    for (int p = 0; p < NPOS - 1; p += 2) {
        // even step: input u (rescaled)
        float y = p2_matvec(bufA, u, FULL);
        {
            int np = (p + 2 < NPOS - 1) ? p + 2 : NPOS - 1;
#pragma unroll
            for (int k = 0; k < 4; k++)
                bufA[k] = *(const float4*)(SbT + (size_t)np * 256 + j * 16 + k * 4);
        }
        float ya = __shfl_sync(FULL, y, 0, 16);
        float us = y * __fdividef(1.0f, ya);
        if (lane < 16) g_v0[(size_t)(b * NPOS + p + 1) * 16 + j] = us;
        if (p + 1 >= NPOS - 1) break;

        // odd step: input y (un-rescaled; fp32 range is safe over 2 steps)
        float y2 = p2_matvec(bufB, y, FULL);
        {
            int np = (p + 3 < NPOS - 1) ? p + 3 : NPOS - 1;
#pragma unroll
            for (int k = 0; k < 4; k++)
                bufB[k] = *(const float4*)(SbT + (size_t)np * 256 + j * 16 + k * 4);
        }
        float y2a = __shfl_sync(FULL, y2, 0, 16);
        float us2 = y2 * __fdividef(1.0f, y2a);
        if (lane < 16) g_v0[(size_t)(b * NPOS + p + 2) * 16 + j] = us2;
        u = us2;
    }
}

// ---------------------------------------------------------------------------
// Phase 3: re-scan, emitting all outputs. Block = 4 warps; each warp = one
// chunk pair (b,p)/(b+16,p) in its half-warps. Unnormalized carry; 1/sum
// folded per step; sum(w) = exp(lZ_{t-1}) -> outputs deferred one iteration.
// ---------------------------------------------------------------------------
__global__ void __launch_bounds__(128) phase3_kernel(
    const float* __restrict__ em, const float* __restrict__ bp,
    const float* __restrict__ mk,
    float* __restrict__ bel, float* __restrict__ lbel, float* __restrict__ lnr)
{
    __shared__ float s_E[4][2][LCH * KK];
    __shared__ float s_cf[4][2][LCH * 8];
    __shared__ float s_mk[4][2][LCH];
    const unsigned FULL = 0xffffffffu;
    int wid = threadIdx.x >> 5, lane = threadIdx.x & 31;
    int hw = lane >> 4, j = lane & 15;
    int pk = blockIdx.x * 4 + wid;
    int b = (pk >> 8) + hw * 16;
    int p = pk & 255;
    size_t base_t = (size_t)b * TT + (size_t)p * LCH;

    // staging: each half-warp stages its own chunk
    {
        const float4* src = (const float4*)(em + base_t * KK);
        float4* dstE = (float4*)s_E[wid][hw];
#pragma unroll
        for (int i = j; i < LCH * KK / 4; i += 16) {
            float4 v = src[i];
            dstE[i] = make_float4(__expf(v.x), __expf(v.y), __expf(v.z), __expf(v.w));
        }
        {
            int i = j;   // LCH == 16: one step per lane
            float bpt = bp[base_t + i];
            float eta = fminf(fmaxf(0.02f + 0.33f * bpt, 0.001f), 0.95f);
            float stay = fmaxf((1.0f - eta) - RHO_C, 0.01f);
            float rm = (RHO_C + stay) + eta;
            float irm = __fdividef(1.0f, rm);
            float4* cf = (float4*)&s_cf[wid][hw][i * 8];
            cf[0] = make_float4(eta - FLOORP, eta * irm - FLOORP,
                                (1.0f - eta) - FLOORP, stay * irm - FLOORP);
            cf[1] = make_float4((1.0f - RHO_C) - FLOORP, RHO_C * irm - FLOORP,
                                RHO_C - FLOORP, 0.0f);
            s_mk[wid][hw][i] = mk[base_t + i];
        }
    }
    __syncwarp();

    float* belb  = bel  + base_t * KK;
    float* lbelb = lbel + base_t * KK;
    float* lnrb  = lnr  + base_t;

    float w;
    int t0;
    if (p == 0) {                          // warp-uniform
        float em0 = __ldg(em + (size_t)b * TT * KK);
        float emj = __ldg(em + (size_t)b * TT * KK + j);
        float m0 = s_mk[wid][hw][0];
        float la0 = (j == 0) ? 0.0f : (NEG_INF_C + emj - em0);
        la0 = m0 * la0 + (1.0f - m0) * ((j == 0) ? 0.0f : NEG_INF_C);
        w = expf(la0);
        belb[j] = w;
        lbelb[j] = la0;
        if (j == 0) lnrb[0] = m0 * em0;    // lZ0 == em[b,0,0] exactly
        t0 = 1;
    } else {
        w = g_v0[(size_t)(b * NPOS + p) * 16 + j];
        t0 = 0;
    }

    for (int tl = t0; tl < LCH; ++tl) {
        const float4* cf = (const float4*)&s_cf[wid][hw][tl * 8];
        float4 ca = cf[0], cb = cf[1];
        float E = s_E[wid][hw][tl * KK + j];

        float c = w;
#pragma unroll
        for (int s = 8; s >= 1; s >>= 1)
            c += __shfl_xor_sync(FULL, c, s, 16);
        float ic = __fdividef(1.0f, c);

        float um1 = __shfl_sync(FULL, w, (j + 15) & 15, 16);
        float up1 = __shfl_sync(FULL, w, (j + 1) & 15, 16);
        float ec = (j == 0) ? 0.0f : (j == 1 ? ca.x : ca.y);
        float dc = (j == 0) ? ca.z : (j == 15 ? cb.x : ca.w);
        float rc = (j == 15) ? 0.0f : (j == 14 ? cb.z : cb.y);
        float q = fmaf(dc, w, fmaf(rc, up1, ec * um1));
        float wn = fmaf(ic, q, FLOORP) * E;

        if (tl > t0) {                     // deferred outputs for t = base+tl-1
            float lZ = __logf(c);
            belb[(tl - 1) * KK + j]  = w * ic;
            lbelb[(tl - 1) * KK + j] = __logf(w) - lZ;
            if (j == 0) lnrb[tl - 1] = s_mk[wid][hw][tl - 1] * lZ;
        }
        w = wn;
    }
    float c = w;
#pragma unroll
    for (int s = 8; s >= 1; s >>= 1)
        c += __shfl_xor_sync(FULL, c, s, 16);
    float ic = __fdividef(1.0f, c);
    float lZ = __logf(c);
    belb[(LCH - 1) * KK + j]  = w * ic;
    lbelb[(LCH - 1) * KK + j] = __logf(w) - lZ;
    if (j == 0) lnrb[LCH - 1] = s_mk[wid][hw][LCH - 1] * lZ;
}

// ---------------------------------------------------------------------------
extern "C" void kernel_launch(void* const* d_in, const int* in_sizes, int n_in,
                              void* d_out, int out_size) {
    const float* em = (const float*)d_in[0];
    const float* bp = (const float*)d_in[1];
    const float* mk = (const float*)d_in[2];
    float* out = (float*)d_out;

    const size_t BTK = (size_t)BB * TT * KK;
    const size_t BT  = (size_t)BB * TT;
    float* bel  = out;
    float* lbel = out + BTK;
    float* lnr  = out + 2 * BTK;
    float* A    = out + 2 * BTK + BT;

    phase1_kernel<<<NPAIR, 128>>>(em, bp, (float4*)A);
    phase2_kernel<<<BB, 32>>>(em, mk);
    phase3_kernel<<<NPAIR / 4, 128>>>(em, bp, mk, bel, lbel, lnr);
}

// round 9
// speedup vs baseline: 1.8730x; 1.8730x over previous
#include <cuda_runtime.h>
#include <cstddef>

#define TT 4096
#define KK 16
#define BB 32
#define LCH 32
#define NPOS (TT / LCH)            // 128 chunks per batch
#define NCHUNK (BB * NPOS)         // 4096 chunks
#define NQUAD (NPOS / 4)           // 32 quads per batch
#define RHO_C 0.001f
#define NEG_INF_C (-1000000.0f)
#define FLOORP 1e-10f

__device__ float g_S[NCHUNK * 256];        // transfer matrix, [chunk][row][col]
__device__ float g_S4[BB * NQUAD * 256];   // quad products
__device__ float g_v0[NCHUNK * 16];        // (rescaled) alpha entering each chunk

// ---------------------------------------------------------------------------
// Phase 1: transfer matrices + fused coalesced A writes (LCH=32).
// Block = 128 threads for chunk pair (bA,p),(bA+16,p):
//   warps 0,1: transfer matrices; warps 2,3: A-block writes (STG.128 coalesced)
// ---------------------------------------------------------------------------
__global__ void __launch_bounds__(128) phase1_kernel(const float* __restrict__ em,
                                                     const float* __restrict__ bp,
                                                     float4* __restrict__ A4) {
    __shared__ float s_E[2][LCH * KK];
    __shared__ float s_cf[2][LCH * 8];
    const unsigned FULL = 0xffffffffu;
    int tid = threadIdx.x;
    int wid = tid >> 5, lane = tid & 31;
    int pk = blockIdx.x;
    int bA = pk >> 7;                 // 0..15
    int p  = pk & 127;

    // stage exp(emissions): 256 float4 total, 2 per thread
    for (int ii = tid; ii < 256; ii += 128) {
        int h = ii >> 7, idx = ii & 127;
        size_t bt = (size_t)(bA + h * 16) * TT + (size_t)p * LCH;
        float4 v = ((const float4*)(em + bt * KK))[idx];
        ((float4*)s_E[h])[idx] = make_float4(__expf(v.x), __expf(v.y), __expf(v.z), __expf(v.w));
    }
    // stage folded coefficients: 64 steps total, one per thread
    if (tid < 64) {
        int h = tid >> 5, i = tid & 31;
        size_t bt = (size_t)(bA + h * 16) * TT + (size_t)p * LCH;
        float bpt = bp[bt + i];
        float eta = fminf(fmaxf(0.02f + 0.33f * bpt, 0.001f), 0.95f);
        float stay = fmaxf((1.0f - eta) - RHO_C, 0.01f);
        float rm = (RHO_C + stay) + eta;
        float irm = __fdividef(1.0f, rm);          // r0 == rl == 1 exactly
        float4* cf = (float4*)&s_cf[h][i * 8];
        cf[0] = make_float4(eta - FLOORP, eta * irm - FLOORP,
                            (1.0f - eta) - FLOORP, stay * irm - FLOORP);
        cf[1] = make_float4((1.0f - RHO_C) - FLOORP, RHO_C * irm - FLOORP,
                            RHO_C - FLOORP, 0.0f);
    }
    __syncthreads();

    if (wid < 2) {
        // ---- transfer matrix for chunk `wid`: lane owns one column ----
        int hl = lane & 15;
        int b = bA + wid * 16;
        float w[16];
#pragma unroll
        for (int r = 0; r < 16; r++) w[r] = (r == hl) ? 1.0f : 0.0f;
        float csum = 1.0f;

        int t0 = (p == 0) ? 1 : 0;
        for (int tl = t0; tl < LCH; ++tl) {
            const float4* cf = (const float4*)&s_cf[wid][tl * 8];
            float4 ca = cf[0], cb = cf[1];
            const float* Et = &s_E[wid][tl * KK];
            float y[16];
#pragma unroll
            for (int r = 0; r < 16; r++) {
                float um1 = w[(r + 15) & 15];
                float up1 = w[(r + 1) & 15];
                float ec = (r == 0) ? 0.0f : (r == 1 ? ca.x : ca.y);
                float dc = (r == 0) ? ca.z : (r == 15 ? cb.x : ca.w);
                float rc = (r == 15) ? 0.0f : (r == 14 ? cb.z : cb.y);
                float q = fmaf(dc, w[r], fmaf(rc, up1, ec * um1));
                float P = fmaf(FLOORP, csum, q);
                y[r] = P * Et[r];
            }
            float a0 = (y[0] + y[4]) + (y[8] + y[12]);
            float a1 = (y[1] + y[5]) + (y[9] + y[13]);
            float a2 = (y[2] + y[6]) + (y[10] + y[14]);
            float a3 = (y[3] + y[7]) + (y[11] + y[15]);
            float cs2 = (a0 + a1) + (a2 + a3);
            float sc = __shfl_sync(FULL, cs2, 0, 16);
            float isc = __fdividef(1.0f, sc);
#pragma unroll
            for (int r = 0; r < 16; r++) w[r] = y[r] * isc;
            csum = cs2 * isc;
        }
        if (lane < 16) {      // store [row][col]
            float* out = g_S + (size_t)(b * NPOS + p) * 256 + hl;
#pragma unroll
            for (int r = 0; r < 16; r++) out[r * 16] = w[r];
        }
    } else {
        // ---- A writes: whole warp per 1KB block, 2 STG.128/lane/step ----
        int h = wid - 2;
        size_t bt0 = (size_t)(bA + h * 16) * TT + (size_t)p * LCH;
        int f0 = lane, f1 = lane + 32;
        int r_0 = f0 >> 2, c0_0 = (f0 & 3) * 4;
        int r_1 = f1 >> 2, c0_1 = (f1 & 3) * 4;
        for (int i = 0; i < LCH; i++) {
            const float4* cf = (const float4*)&s_cf[h][i * 8];
            float4 ca = cf[0], cb = cf[1];
            float4* blk = A4 + (bt0 + i) * 64;
#pragma unroll
            for (int rep = 0; rep < 2; rep++) {
                int r  = rep ? r_1 : r_0;
                int c0 = rep ? c0_1 : c0_0;
                float dg = ((r == 0) ? ca.z : (r == 15) ? cb.x : ca.w) + FLOORP;
                float ev = ((r == 0) ? ca.x : ca.y) + FLOORP;
                float rv = ((r == 15) ? cb.z : cb.y) + FLOORP;
                float x[4];
#pragma unroll
                for (int q = 0; q < 4; q++) {
                    int j = c0 + q;
                    x[q] = (j == r) ? dg : (j == r + 1) ? ev : (j == r - 1) ? rv : 0.0f;
                }
                blk[rep ? f1 : f0] = make_float4(x[0], x[1], x[2], x[3]);
            }
        }
    }
}

// ---------------------------------------------------------------------------
// Compose: S4[q] = S[4q+3]*S[4q+2]*S[4q+1]*S[4q], rescaled after each matmul.
// One block (256 threads) per quad; thread = one output element.
// ---------------------------------------------------------------------------
__global__ void __launch_bounds__(256) compose_kernel() {
    __shared__ float sM[4][256];
    __shared__ float sP[256];
    __shared__ float sQ[256];
    int tid = threadIdx.x;
    int quad = blockIdx.x;
    int b = quad >> 5, q = quad & 31;
    const float* S0 = g_S + ((size_t)b * NPOS + q * 4) * 256;
#pragma unroll
    for (int m = 0; m < 4; m++) sM[m][tid] = S0[m * 256 + tid];
    __syncthreads();

    int r = tid >> 4, c = tid & 15;
    float acc = 0.0f;
#pragma unroll
    for (int k = 0; k < 16; k++) acc = fmaf(sM[1][r * 16 + k], sM[0][k * 16 + c], acc);
    sP[tid] = acc;
    __syncthreads();
    float inv1 = __fdividef(1.0f, sP[0]);
    acc = 0.0f;
#pragma unroll
    for (int k = 0; k < 16; k++) acc = fmaf(sM[2][r * 16 + k], sP[k * 16 + c], acc);
    acc *= inv1;
    sQ[tid] = acc;
    __syncthreads();
    float inv2 = __fdividef(1.0f, sQ[0]);
    acc = 0.0f;
#pragma unroll
    for (int k = 0; k < 16; k++) acc = fmaf(sM[3][r * 16 + k], sQ[k * 16 + c], acc);
    g_S4[(size_t)quad * 256 + tid] = acc * inv2;
}

// ---------------------------------------------------------------------------
// Phase 2: per batch — 31-step serial chain over smem-resident S4 (warp 0),
// then all 16 half-warps fill intra-quad start vectors (3 matvecs each quad).
// ---------------------------------------------------------------------------
__global__ void __launch_bounds__(256) phase2_kernel(const float* __restrict__ em,
                                                     const float* __restrict__ mk) {
    __shared__ float sS4[(NQUAD - 1) * 256];   // 31 KB
    __shared__ float s_v0[NQUAD][16];
    const unsigned FULL = 0xffffffffu;
    int b = blockIdx.x;
    int tid = threadIdx.x;
    int j = tid & 15;

    for (int i = tid; i < (NQUAD - 1) * 256; i += 256)
        sS4[i] = g_S4[(size_t)b * NQUAD * 256 + i];
    __syncthreads();

    if (tid < 32) {   // warp 0: serial chain (lanes mirror via j = lane&15)
        float em0 = __ldg(em + (size_t)b * TT * KK);
        float emj = __ldg(em + (size_t)b * TT * KK + j);
        float m0 = __ldg(mk + (size_t)b * TT);
        float la0 = (j == 0) ? 0.0f : (NEG_INF_C + emj - em0);
        la0 = m0 * la0 + (1.0f - m0) * ((j == 0) ? 0.0f : NEG_INF_C);
        float u = expf(la0);
        if (tid < 16) {
            s_v0[0][j] = u;
            g_v0[(size_t)(b * NPOS) * 16 + j] = u;
        }
        for (int k = 0; k < NQUAD - 1; ++k) {
            const float4* row = (const float4*)&sS4[k * 256 + j * 16];
            float4 m0v = row[0], m1v = row[1], m2v = row[2], m3v = row[3];
            float y0 = 0.f, y1 = 0.f, y2 = 0.f, y3 = 0.f;
            y0 = fmaf(m0v.x, __shfl_sync(FULL, u, 0, 16), y0);
            y1 = fmaf(m0v.y, __shfl_sync(FULL, u, 1, 16), y1);
            y2 = fmaf(m0v.z, __shfl_sync(FULL, u, 2, 16), y2);
            y3 = fmaf(m0v.w, __shfl_sync(FULL, u, 3, 16), y3);
            y0 = fmaf(m1v.x, __shfl_sync(FULL, u, 4, 16), y0);
            y1 = fmaf(m1v.y, __shfl_sync(FULL, u, 5, 16), y1);
            y2 = fmaf(m1v.z, __shfl_sync(FULL, u, 6, 16), y2);
            y3 = fmaf(m1v.w, __shfl_sync(FULL, u, 7, 16), y3);
            y0 = fmaf(m2v.x, __shfl_sync(FULL, u, 8, 16), y0);
            y1 = fmaf(m2v.y, __shfl_sync(FULL, u, 9, 16), y1);
            y2 = fmaf(m2v.z, __shfl_sync(FULL, u, 10, 16), y2);
            y3 = fmaf(m2v.w, __shfl_sync(FULL, u, 11, 16), y3);
            y0 = fmaf(m3v.x, __shfl_sync(FULL, u, 12, 16), y0);
            y1 = fmaf(m3v.y, __shfl_sync(FULL, u, 13, 16), y1);
            y2 = fmaf(m3v.z, __shfl_sync(FULL, u, 14, 16), y2);
            y3 = fmaf(m3v.w, __shfl_sync(FULL, u, 15, 16), y3);
            float y = (y0 + y1) + (y2 + y3);
            float ya = __shfl_sync(FULL, y, 0, 16);
            u = y * __fdividef(1.0f, ya);
            if (tid < 16) {
                s_v0[k + 1][j] = u;
                g_v0[(size_t)(b * NPOS + 4 * (k + 1)) * 16 + j] = u;
            }
        }
    }
    __syncthreads();

    // fill positions 4q+1..4q+3: 16 half-warps x 2 quads each
    int hwid = tid >> 4;
#pragma unroll
    for (int rep = 0; rep < 2; rep++) {
        int q = hwid * 2 + rep;
        // prefetch rows of S[4q], S[4q+1], S[4q+2]
        float4 rw[3][4];
#pragma unroll
        for (int s = 0; s < 3; s++) {
            const float4* src = (const float4*)(g_S + ((size_t)b * NPOS + 4 * q + s) * 256 + j * 16);
#pragma unroll
            for (int k = 0; k < 4; k++) rw[s][k] = src[k];
        }
        float u = s_v0[q][j];
#pragma unroll
        for (int s = 0; s < 3; s++) {
            float y0 = 0.f, y1 = 0.f, y2 = 0.f, y3 = 0.f;
#pragma unroll
            for (int k = 0; k < 4; k++) {
                y0 = fmaf(rw[s][k].x, __shfl_sync(FULL, u, k * 4 + 0, 16), y0);
                y1 = fmaf(rw[s][k].y, __shfl_sync(FULL, u, k * 4 + 1, 16), y1);
                y2 = fmaf(rw[s][k].z, __shfl_sync(FULL, u, k * 4 + 2, 16), y2);
                y3 = fmaf(rw[s][k].w, __shfl_sync(FULL, u, k * 4 + 3, 16), y3);
            }
            float y = (y0 + y1) + (y2 + y3);
            float ya = __shfl_sync(FULL, y, 0, 16);
            u = y * __fdividef(1.0f, ya);
            g_v0[(size_t)(b * NPOS + 4 * q + s + 1) * 16 + j] = u;
        }
    }
}

// ---------------------------------------------------------------------------
// Phase 3: re-scan, emitting all outputs. Block = 4 warps; warp = chunk pair
// (b,p)/(b+16,p) in half-warps. Unnormalized carry; outputs deferred one step.
// ---------------------------------------------------------------------------
__global__ void __launch_bounds__(128) phase3_kernel(
    const float* __restrict__ em, const float* __restrict__ bp,
    const float* __restrict__ mk,
    float* __restrict__ bel, float* __restrict__ lbel, float* __restrict__ lnr)
{
    __shared__ float s_E[4][2][LCH * KK];
    __shared__ float s_cf[4][2][LCH * 8];
    __shared__ float s_mk[4][2][LCH];
    const unsigned FULL = 0xffffffffu;
    int wid = threadIdx.x >> 5, lane = threadIdx.x & 31;
    int hw = lane >> 4, j = lane & 15;
    int pk = blockIdx.x * 4 + wid;
    int b = (pk >> 7) + hw * 16;
    int p = pk & 127;
    size_t base_t = (size_t)b * TT + (size_t)p * LCH;

    {
        const float4* src = (const float4*)(em + base_t * KK);
        float4* dstE = (float4*)s_E[wid][hw];
#pragma unroll
        for (int i = j; i < LCH * KK / 4; i += 16) {
            float4 v = src[i];
            dstE[i] = make_float4(__expf(v.x), __expf(v.y), __expf(v.z), __expf(v.w));
        }
#pragma unroll
        for (int i = j; i < LCH; i += 16) {
            float bpt = bp[base_t + i];
            float eta = fminf(fmaxf(0.02f + 0.33f * bpt, 0.001f), 0.95f);
            float stay = fmaxf((1.0f - eta) - RHO_C, 0.01f);
            float rm = (RHO_C + stay) + eta;
            float irm = __fdividef(1.0f, rm);
            float4* cf = (float4*)&s_cf[wid][hw][i * 8];
            cf[0] = make_float4(eta - FLOORP, eta * irm - FLOORP,
                                (1.0f - eta) - FLOORP, stay * irm - FLOORP);
            cf[1] = make_float4((1.0f - RHO_C) - FLOORP, RHO_C * irm - FLOORP,
                                RHO_C - FLOORP, 0.0f);
            s_mk[wid][hw][i] = mk[base_t + i];
        }
    }
    __syncwarp();

    float* belb  = bel  + base_t * KK;
    float* lbelb = lbel + base_t * KK;
    float* lnrb  = lnr  + base_t;

    float w;
    int t0;
    if (p == 0) {
        float em0 = __ldg(em + (size_t)b * TT * KK);
        float emj = __ldg(em + (size_t)b * TT * KK + j);
        float m0 = s_mk[wid][hw][0];
        float la0 = (j == 0) ? 0.0f : (NEG_INF_C + emj - em0);
        la0 = m0 * la0 + (1.0f - m0) * ((j == 0) ? 0.0f : NEG_INF_C);
        w = expf(la0);
        belb[j] = w;
        lbelb[j] = la0;
        if (j == 0) lnrb[0] = m0 * em0;
        t0 = 1;
    } else {
        w = g_v0[(size_t)(b * NPOS + p) * 16 + j];
        t0 = 0;
    }

    for (int tl = t0; tl < LCH; ++tl) {
        const float4* cf = (const float4*)&s_cf[wid][hw][tl * 8];
        float4 ca = cf[0], cb = cf[1];
        float E = s_E[wid][hw][tl * KK + j];

        float c = w;
#pragma unroll
        for (int s = 8; s >= 1; s >>= 1)
            c += __shfl_xor_sync(FULL, c, s, 16);
        float ic = __fdividef(1.0f, c);

        float um1 = __shfl_sync(FULL, w, (j + 15) & 15, 16);
        float up1 = __shfl_sync(FULL, w, (j + 1) & 15, 16);
        float ec = (j == 0) ? 0.0f : (j == 1 ? ca.x : ca.y);
        float dc = (j == 0) ? ca.z : (j == 15 ? cb.x : ca.w);
        float rc = (j == 15) ? 0.0f : (j == 14 ? cb.z : cb.y);
        float q = fmaf(dc, w, fmaf(rc, up1, ec * um1));
        float wn = fmaf(ic, q, FLOORP) * E;

        if (tl > t0) {
            float lZ = __logf(c);
            belb[(tl - 1) * KK + j]  = w * ic;
            lbelb[(tl - 1) * KK + j] = __logf(w) - lZ;
            if (j == 0) lnrb[tl - 1] = s_mk[wid][hw][tl - 1] * lZ;
        }
        w = wn;
    }
    float c = w;
#pragma unroll
    for (int s = 8; s >= 1; s >>= 1)
        c += __shfl_xor_sync(FULL, c, s, 16);
    float ic = __fdividef(1.0f, c);
    float lZ = __logf(c);
    belb[(LCH - 1) * KK + j]  = w * ic;
    lbelb[(LCH - 1) * KK + j] = __logf(w) - lZ;
    if (j == 0) lnrb[LCH - 1] = s_mk[wid][hw][LCH - 1] * lZ;
}

// ---------------------------------------------------------------------------
extern "C" void kernel_launch(void* const* d_in, const int* in_sizes, int n_in,
                              void* d_out, int out_size) {
    const float* em = (const float*)d_in[0];
    const float* bp = (const float*)d_in[1];
    const float* mk = (const float*)d_in[2];
    float* out = (float*)d_out;

    const size_t BTK = (size_t)BB * TT * KK;
    const size_t BT  = (size_t)BB * TT;
    float* bel  = out;
    float* lbel = out + BTK;
    float* lnr  = out + 2 * BTK;
    float* A    = out + 2 * BTK + BT;

    phase1_kernel<<<NCHUNK / 2, 128>>>(em, bp, (float4*)A);
    compose_kernel<<<BB * NQUAD, 256>>>();
    phase2_kernel<<<BB, 256>>>(em, mk);
    phase3_kernel<<<NCHUNK / 8, 128>>>(em, bp, mk, bel, lbel, lnr);
}